// round 1
// baseline (speedup 1.0000x reference)
#include <cuda_runtime.h>
#include <cuda_fp16.h>
#include <cstdint>

// Problem constants
namespace {
constexpr int  Bn     = 8;
constexpr long Tn     = 262144;
constexpr long Sn     = 131072;   // output sequence length
constexpr int  En     = 128;      // conv channels / GEMM K
constexpr int  Pn     = 64;       // output features / GEMM N
constexpr int  S_TILE = 128;      // positions per CTA (GEMM M)
constexpr int  THREADS= 256;
constexpr int  LDA    = 136;      // halves per row (128 + 8 pad) -> conflict-free ldmatrix
constexpr int  LDW    = 136;

// shared memory layout (bytes)
constexpr int SMEM_XS  = 0;                              // 259 floats (window), pad to 1152
constexpr int SMEM_FHI = 1152;
constexpr int SMEM_FLO = SMEM_FHI + S_TILE * LDA * 2;    // +34816
constexpr int SMEM_WHI = SMEM_FLO + S_TILE * LDA * 2;    // +34816
constexpr int SMEM_WLO = SMEM_WHI + Pn * LDW * 2;        // +17408
constexpr int SMEM_LB  = SMEM_WLO + Pn * LDW * 2;        // +17408
constexpr int SMEM_TOTAL = SMEM_LB + Pn * 4;             // +256  => 105856 B
}

__device__ __forceinline__ uint32_t smem_u32(const void* p) {
    return (uint32_t)__cvta_generic_to_shared(p);
}

#define LDSM_X4(r0, r1, r2, r3, addr)                                          \
    asm volatile("ldmatrix.sync.aligned.m8n8.x4.shared.b16 {%0,%1,%2,%3}, [%4];" \
                 : "=r"(r0), "=r"(r1), "=r"(r2), "=r"(r3) : "r"(addr))

#define MMA16816(d, a0, a1, a2, a3, b0, b1)                                    \
    asm volatile("mma.sync.aligned.m16n8k16.row.col.f32.f16.f16.f32 "          \
                 "{%0,%1,%2,%3},{%4,%5,%6,%7},{%8,%9},{%0,%1,%2,%3};"          \
                 : "+f"((d)[0]), "+f"((d)[1]), "+f"((d)[2]), "+f"((d)[3])      \
                 : "r"(a0), "r"(a1), "r"(a2), "r"(a3), "r"(b0), "r"(b1))

__global__ void __launch_bounds__(THREADS, 2)
encoder_kernel(const float* __restrict__ x,       // [B, T]
               const float* __restrict__ conv_w,  // [128, 1, 5]
               const float* __restrict__ conv_b,  // [128]
               const float* __restrict__ lin_w,   // [64, 128]
               const float* __restrict__ lin_b,   // [64]
               float* __restrict__ out)           // [B, S, 64]
{
    extern __shared__ char smem[];
    float*  xs  = (float*)(smem + SMEM_XS);
    __half* fhi = (__half*)(smem + SMEM_FHI);
    __half* flo = (__half*)(smem + SMEM_FLO);
    __half* whi = (__half*)(smem + SMEM_WHI);
    __half* wlo = (__half*)(smem + SMEM_WLO);
    float*  lb  = (float*)(smem + SMEM_LB);

    const int tid = threadIdx.x;
    const int b   = blockIdx.y;
    const int s0  = blockIdx.x * S_TILE;

    // ---- stage input window + split linear weights ----
    {
        const long t0 = 2L * s0 - 2;                 // xs[i] <-> time t0+i
        const float* xb = x + (long)b * Tn;
        for (int i = tid; i < 2 * S_TILE + 3; i += THREADS) {
            long t = t0 + i;
            xs[i] = (t >= 0 && t < Tn) ? xb[t] : 0.f;
        }
        for (int i = tid; i < Pn * En; i += THREADS) {
            float w = lin_w[i];
            __half hi = __float2half_rn(w);
            __half lo = __float2half_rn(w - __half2float(hi));
            int p = i >> 7, e = i & 127;
            whi[p * LDW + e] = hi;
            wlo[p * LDW + e] = lo;
        }
        if (tid < Pn) lb[tid] = lin_b[tid];
    }

    // per-thread conv channel + taps in registers
    const int ch = tid & 127;
    const int ph = tid >> 7;   // position half: 0 -> rows 0..63, 1 -> rows 64..127
    const float wk0 = conv_w[ch * 5 + 0];
    const float wk1 = conv_w[ch * 5 + 1];
    const float wk2 = conv_w[ch * 5 + 2];
    const float wk3 = conv_w[ch * 5 + 3];
    const float wk4 = conv_w[ch * 5 + 4];
    const float cb  = conv_b[ch];

    __syncthreads();

    // ---- conv1d + ReLU + fp16 hi/lo split into smem ----
    {
#pragma unroll 8
        for (int pp = 0; pp < 64; pp++) {
            int pos = ph * 64 + pp;
            const float* xw = xs + 2 * pos;   // window for this position
            float c = fmaf(wk0, xw[0], cb);
            c = fmaf(wk1, xw[1], c);
            c = fmaf(wk2, xw[2], c);
            c = fmaf(wk3, xw[3], c);
            c = fmaf(wk4, xw[4], c);
            c = fmaxf(c, 0.f);
            __half hi = __float2half_rn(c);
            __half lo = __float2half_rn(c - __half2float(hi));
            fhi[pos * LDA + ch] = hi;
            flo[pos * LDA + ch] = lo;
        }
    }
    __syncthreads();

    // ---- GEMM: out[128 x 64] = relu_feats[128 x 128] @ lin_w^T, fp16-split x3 ----
    const int wid  = tid >> 5;
    const int lane = tid & 31;
    const int m0   = wid * 16;

    float acc[8][4];
#pragma unroll
    for (int j = 0; j < 8; j++)
#pragma unroll
        for (int q = 0; q < 4; q++) acc[j][q] = 0.f;

    // A ldmatrix.x4: mats = {rows m0..+7 klo, m0+8..+15 klo, m0..+7 khi, m0+8..+15 khi}
    const int a_off = (m0 + (lane & 15)) * LDA + ((lane >> 4) << 3);
    // B ldmatrix.x4 over two n8 tiles: rows are n-index, cols are k (W stored [p][e])
    const int b_row = (lane & 7) + ((lane >> 1) & 8);  // +8 when lane>=16 (2nd n-tile)
    const int b_col = (lane & 8);                      // +8 halves for k-high mats
    const int b_off = b_row * LDW + b_col;

    const __half* Asrc[3] = {fhi, flo, fhi};
    const __half* Wsrc[3] = {whi, whi, wlo};

#pragma unroll
    for (int pass = 0; pass < 3; pass++) {
        const uint32_t abase = smem_u32(Asrc[pass] + a_off);
        const uint32_t wbase = smem_u32(Wsrc[pass] + b_off);
#pragma unroll
        for (int k0 = 0; k0 < En; k0 += 16) {
            uint32_t a0, a1, a2, a3;
            LDSM_X4(a0, a1, a2, a3, abase + k0 * 2);
#pragma unroll
            for (int jp = 0; jp < 4; jp++) {
                uint32_t b0, b1, b2, b3;
                LDSM_X4(b0, b1, b2, b3, wbase + (jp * 16 * LDW + k0) * 2);
                MMA16816(acc[2 * jp + 0], a0, a1, a2, a3, b0, b1);
                MMA16816(acc[2 * jp + 1], a0, a1, a2, a3, b2, b3);
            }
        }
    }

    // ---- epilogue: bias + store (8B per lane per row-chunk, 32B sectors) ----
    const int gid = lane >> 2, tig = lane & 3;
    float* obase = out + ((long)b * Sn + s0 + m0 + gid) * Pn;
#pragma unroll
    for (int j = 0; j < 8; j++) {
        int col = j * 8 + tig * 2;
        float bb0 = lb[col], bb1 = lb[col + 1];
        float2 v0 = make_float2(acc[j][0] + bb0, acc[j][1] + bb1);
        float2 v1 = make_float2(acc[j][2] + bb0, acc[j][3] + bb1);
        *reinterpret_cast<float2*>(obase + col) = v0;
        *reinterpret_cast<float2*>(obase + 8 * Pn + col) = v1;
    }
}

extern "C" void kernel_launch(void* const* d_in, const int* in_sizes, int n_in,
                              void* d_out, int out_size) {
    (void)in_sizes; (void)n_in; (void)out_size;
    const float* x      = (const float*)d_in[0];
    const float* conv_w = (const float*)d_in[1];
    const float* conv_b = (const float*)d_in[2];
    const float* lin_w  = (const float*)d_in[3];
    const float* lin_b  = (const float*)d_in[4];
    float* out = (float*)d_out;

    cudaFuncSetAttribute(encoder_kernel,
                         cudaFuncAttributeMaxDynamicSharedMemorySize, SMEM_TOTAL);

    dim3 grid((unsigned)(Sn / S_TILE), Bn);
    encoder_kernel<<<grid, THREADS, SMEM_TOTAL>>>(x, conv_w, conv_b, lin_w, lin_b, out);
}

// round 4
// speedup vs baseline: 1.2953x; 1.2953x over previous
#include <cuda_runtime.h>
#include <cuda_fp16.h>
#include <cstdint>
#include <cstring>

namespace {
constexpr int  Bn = 8;
constexpr long Tn = 262144;
constexpr long Sn = 131072;   // output positions
constexpr int  En = 128;      // conv channels = GEMM K
constexpr int  Pn = 64;       // out features  = GEMM N
constexpr int  S_TILE = 128;  // GEMM M per CTA
constexpr int  THREADS = 256;
constexpr int  LDA = 136;     // halves/row, padded -> conflict-free ldmatrix
constexpr int  LDW = 136;

// smem byte offsets (all 16B aligned)
constexpr int SMEM_XS  = 0;                      // 259 floats
constexpr int SMEM_LB  = 1056;                   // 64 floats
constexpr int SMEM_FHI = 1312;                   // 128 x 136 f16
constexpr int SMEM_FLO = SMEM_FHI + S_TILE * LDA * 2;   // +34816
constexpr int SMEM_WHI = SMEM_FLO + S_TILE * LDA * 2;   // +34816
constexpr int SMEM_WLO = SMEM_WHI + Pn * LDW * 2;       // +17408
constexpr int SMEM_TOTAL = SMEM_WLO + Pn * LDW * 2;     // 105760 B -> 2 CTAs/SM
}

__device__ __forceinline__ uint32_t smem_u32(const void* p) {
    return (uint32_t)__cvta_generic_to_shared(p);
}

#define LDSM_X4(r0, r1, r2, r3, addr)                                            \
    asm volatile("ldmatrix.sync.aligned.m8n8.x4.shared.b16 {%0,%1,%2,%3}, [%4];" \
                 : "=r"(r0), "=r"(r1), "=r"(r2), "=r"(r3) : "r"(addr))

#define MMA16816(d, a0, a1, a2, a3, b0, b1)                                      \
    asm volatile("mma.sync.aligned.m16n8k16.row.col.f32.f16.f16.f32 "            \
                 "{%0,%1,%2,%3},{%4,%5,%6,%7},{%8,%9},{%0,%1,%2,%3};"            \
                 : "+f"((d)[0]), "+f"((d)[1]), "+f"((d)[2]), "+f"((d)[3])        \
                 : "r"(a0), "r"(a1), "r"(a2), "r"(a3), "r"(b0), "r"(b1))

__global__ void __launch_bounds__(THREADS, 2)
encoder_kernel(const float* __restrict__ x,       // [B, T]
               const float* __restrict__ conv_w,  // [128, 1, 5]
               const float* __restrict__ conv_b,  // [128]
               const float* __restrict__ lin_w,   // [64, 128]
               const float* __restrict__ lin_b,   // [64]
               float* __restrict__ out)           // [B, S, 64]
{
    extern __shared__ char smem[];
    float*  xs  = (float*)(smem + SMEM_XS);
    float*  lb  = (float*)(smem + SMEM_LB);
    __half* fhi = (__half*)(smem + SMEM_FHI);
    __half* flo = (__half*)(smem + SMEM_FLO);
    __half* whi = (__half*)(smem + SMEM_WHI);
    __half* wlo = (__half*)(smem + SMEM_WLO);

    const int tid  = threadIdx.x;
    const int wid  = tid >> 5;
    const int lane = tid & 31;
    const int b    = blockIdx.y;
    const int s0   = blockIdx.x * S_TILE;

    // ---- stage: input window, bias, fp16-split linear weights ----
    {
        const long t0 = 2L * s0 - 2;
        const float* xb = x + (long)b * Tn;
        for (int i = tid; i < 2 * S_TILE + 3; i += THREADS) {
            long t = t0 + i;
            xs[i] = (t >= 0 && t < Tn) ? xb[t] : 0.f;
        }
        if (tid < Pn) lb[tid] = lin_b[tid];
        for (int i = tid; i < Pn * (En / 2); i += THREADS) {  // half2 pairs
            int p = i >> 6, e2 = i & 63;
            float2 w = *reinterpret_cast<const float2*>(lin_w + p * En + 2 * e2);
            __half h0 = __float2half_rn(w.x), h1 = __float2half_rn(w.y);
            __half l0 = __float2half_rn(w.x - __half2float(h0));
            __half l1 = __float2half_rn(w.y - __half2float(h1));
            int o = p * LDW + 2 * e2;
            *reinterpret_cast<__half2*>(whi + o) = __halves2half2(h0, h1);
            *reinterpret_cast<__half2*>(wlo + o) = __halves2half2(l0, l1);
        }
    }

    // ---- conv taps: 4 channels per lane (vectorized loads) ----
    const int c0 = 4 * lane;        // channels c0..c0+3
    const int pb = wid * 16;        // 16 positions per thread
    float w[4][5], cb[4];
    {
        const float4* cw4 = reinterpret_cast<const float4*>(conv_w + 5 * c0);
        float4 q0 = cw4[0], q1 = cw4[1], q2 = cw4[2], q3 = cw4[3], q4 = cw4[4];
        w[0][0]=q0.x; w[0][1]=q0.y; w[0][2]=q0.z; w[0][3]=q0.w; w[0][4]=q1.x;
        w[1][0]=q1.y; w[1][1]=q1.z; w[1][2]=q1.w; w[1][3]=q2.x; w[1][4]=q2.y;
        w[2][0]=q2.z; w[2][1]=q2.w; w[2][2]=q3.x; w[2][3]=q3.y; w[2][4]=q3.z;
        w[3][0]=q3.w; w[3][1]=q4.x; w[3][2]=q4.y; w[3][3]=q4.z; w[3][4]=q4.w;
        float4 bb = *reinterpret_cast<const float4*>(conv_b + c0);
        cb[0]=bb.x; cb[1]=bb.y; cb[2]=bb.z; cb[3]=bb.w;
    }

    __syncthreads();   // xs staged

    // ---- conv1d + ReLU + fp16 hi/lo split -> padded A tiles (STS.64) ----
    {
        const float* xw = xs + 2 * pb;   // broadcast reads within warp
        float x0 = xw[0], x1 = xw[1], x2 = xw[2], x3 = xw[3], x4 = xw[4];
#pragma unroll
        for (int p = 0; p < 16; p++) {
            __half2 vh[2], vl[2];
#pragma unroll
            for (int j = 0; j < 2; j++) {
                float f0 = fmaf(w[2*j][0], x0, cb[2*j]);
                f0 = fmaf(w[2*j][1], x1, f0);
                f0 = fmaf(w[2*j][2], x2, f0);
                f0 = fmaf(w[2*j][3], x3, f0);
                f0 = fmaf(w[2*j][4], x4, f0);
                f0 = fmaxf(f0, 0.f);
                float f1 = fmaf(w[2*j+1][0], x0, cb[2*j+1]);
                f1 = fmaf(w[2*j+1][1], x1, f1);
                f1 = fmaf(w[2*j+1][2], x2, f1);
                f1 = fmaf(w[2*j+1][3], x3, f1);
                f1 = fmaf(w[2*j+1][4], x4, f1);
                f1 = fmaxf(f1, 0.f);
                __half h0 = __float2half_rn(f0), h1 = __float2half_rn(f1);
                __half l0 = __float2half_rn(f0 - __half2float(h0));
                __half l1 = __float2half_rn(f1 - __half2float(h1));
                vh[j] = __halves2half2(h0, h1);
                vl[j] = __halves2half2(l0, l1);
            }
            const int o = (pb + p) * LDA + c0;
            *reinterpret_cast<uint2*>(fhi + o) = *reinterpret_cast<const uint2*>(vh);
            *reinterpret_cast<uint2*>(flo + o) = *reinterpret_cast<const uint2*>(vl);
            if (p < 15) {
                x0 = x2; x1 = x3; x2 = x4;
                x3 = xw[2 * p + 5]; x4 = xw[2 * p + 6];
            }
        }
    }
    __syncthreads();

    // ---- GEMM: 8 warps tiled 4m x 2n, each m32 x n32, 3-term fp16 split ----
    const int m0 = (wid & 3) * 32;
    const int n0 = (wid >> 2) * 32;

    float acc[2][4][4];
#pragma unroll
    for (int mt = 0; mt < 2; mt++)
#pragma unroll
        for (int nt = 0; nt < 4; nt++)
#pragma unroll
            for (int q = 0; q < 4; q++) acc[mt][nt][q] = 0.f;

    // ldmatrix lane offsets (halves)
    const int aoff0 = (m0 + (lane & 15)) * LDA + ((lane >> 4) << 3);
    const int aoff1 = aoff0 + 16 * LDA;
    const int brow  = (lane & 7) + ((lane >> 4) << 3);
    const int bcol  = ((lane >> 3) & 1) << 3;
    const int boff0 = (n0 + brow) * LDW + bcol;
    const int boff1 = boff0 + 16 * LDW;

    const uint32_t fhi_a0 = smem_u32(fhi + aoff0), fhi_a1 = smem_u32(fhi + aoff1);
    const uint32_t flo_a0 = smem_u32(flo + aoff0), flo_a1 = smem_u32(flo + aoff1);
    const uint32_t whi_b0 = smem_u32(whi + boff0), whi_b1 = smem_u32(whi + boff1);
    const uint32_t wlo_b0 = smem_u32(wlo + boff0), wlo_b1 = smem_u32(wlo + boff1);

#pragma unroll
    for (int c = 0; c < 8; c++) {
        const uint32_t kB = c * 32;  // k-chunk byte offset (16 halves)

        uint32_t ah[2][4], al[2][4], bh[2][4], bl[2][4];
        LDSM_X4(ah[0][0], ah[0][1], ah[0][2], ah[0][3], fhi_a0 + kB);
        LDSM_X4(ah[1][0], ah[1][1], ah[1][2], ah[1][3], fhi_a1 + kB);
        LDSM_X4(al[0][0], al[0][1], al[0][2], al[0][3], flo_a0 + kB);
        LDSM_X4(al[1][0], al[1][1], al[1][2], al[1][3], flo_a1 + kB);
        LDSM_X4(bh[0][0], bh[0][1], bh[0][2], bh[0][3], whi_b0 + kB);
        LDSM_X4(bh[1][0], bh[1][1], bh[1][2], bh[1][3], whi_b1 + kB);
        LDSM_X4(bl[0][0], bl[0][1], bl[0][2], bl[0][3], wlo_b0 + kB);
        LDSM_X4(bl[1][0], bl[1][1], bl[1][2], bl[1][3], wlo_b1 + kB);

#pragma unroll
        for (int mt = 0; mt < 2; mt++) {
#pragma unroll
            for (int np = 0; np < 2; np++) {
                // n-tile 2*np   : regs {b0,b1};  n-tile 2*np+1 : regs {b2,b3}
                MMA16816(acc[mt][2*np+0], ah[mt][0], ah[mt][1], ah[mt][2], ah[mt][3],
                         bh[np][0], bh[np][1]);
                MMA16816(acc[mt][2*np+1], ah[mt][0], ah[mt][1], ah[mt][2], ah[mt][3],
                         bh[np][2], bh[np][3]);
                MMA16816(acc[mt][2*np+0], al[mt][0], al[mt][1], al[mt][2], al[mt][3],
                         bh[np][0], bh[np][1]);
                MMA16816(acc[mt][2*np+1], al[mt][0], al[mt][1], al[mt][2], al[mt][3],
                         bh[np][2], bh[np][3]);
                MMA16816(acc[mt][2*np+0], ah[mt][0], ah[mt][1], ah[mt][2], ah[mt][3],
                         bl[np][0], bl[np][1]);
                MMA16816(acc[mt][2*np+1], ah[mt][0], ah[mt][1], ah[mt][2], ah[mt][3],
                         bl[np][2], bl[np][3]);
            }
        }
    }

    // ---- epilogue: bias + float2 stores ----
    const int gid = lane >> 2, tig = lane & 3;
#pragma unroll
    for (int mt = 0; mt < 2; mt++) {
        const int row = s0 + m0 + mt * 16 + gid;
        float* ob = out + ((long)b * Sn + row) * Pn;
#pragma unroll
        for (int nt = 0; nt < 4; nt++) {
            const int col = n0 + nt * 8 + tig * 2;
            const float bb0 = lb[col], bb1 = lb[col + 1];
            float2 v0 = make_float2(acc[mt][nt][0] + bb0, acc[mt][nt][1] + bb1);
            float2 v1 = make_float2(acc[mt][nt][2] + bb0, acc[mt][nt][3] + bb1);
            *reinterpret_cast<float2*>(ob + col) = v0;
            *reinterpret_cast<float2*>(ob + 8 * Pn + col) = v1;
        }
    }
}

extern "C" void kernel_launch(void* const* d_in, const int* in_sizes, int n_in,
                              void* d_out, int out_size) {
    (void)in_sizes; (void)n_in; (void)out_size;
    const float* x      = (const float*)d_in[0];
    const float* conv_w = (const float*)d_in[1];
    const float* conv_b = (const float*)d_in[2];
    const float* lin_w  = (const float*)d_in[3];
    const float* lin_b  = (const float*)d_in[4];
    float* out = (float*)d_out;

    cudaFuncSetAttribute(encoder_kernel,
                         cudaFuncAttributeMaxDynamicSharedMemorySize, SMEM_TOTAL);

    dim3 grid((unsigned)(Sn / S_TILE), Bn);
    encoder_kernel<<<grid, THREADS, SMEM_TOTAL>>>(x, conv_w, conv_b, lin_w, lin_b, out);
}

// round 5
// speedup vs baseline: 2.3867x; 1.8426x over previous
#include <cuda_runtime.h>
#include <cuda_fp16.h>
#include <cstdint>

namespace {
constexpr int  Bn = 8;
constexpr long Tn = 262144;
constexpr long Sn = 131072;   // output positions
constexpr int  En = 128;      // conv channels = GEMM K
constexpr int  Pn = 64;       // out features  = GEMM N
constexpr int  S_TILE = 128;  // GEMM M per CTA
constexpr int  THREADS = 256;
constexpr int  LDA = 136;     // halves/row, padded -> conflict-free ldmatrix
constexpr int  LDW = 136;

// smem byte offsets (16B aligned)
constexpr int SMEM_XS  = 0;                           // 259 floats
constexpr int SMEM_LB  = 1056;                        // 64 floats
constexpr int SMEM_FHI = 1312;                        // 128 x 136 f16 = 34816
constexpr int SMEM_WHI = SMEM_FHI + S_TILE * LDA * 2; // 64 x 136 f16 = 17408
constexpr int SMEM_TOTAL = SMEM_WHI + Pn * LDW * 2;   // 53536 B -> 4 CTAs/SM
}

__device__ __forceinline__ uint32_t smem_u32(const void* p) {
    return (uint32_t)__cvta_generic_to_shared(p);
}

#define LDSM_X4(r0, r1, r2, r3, addr)                                            \
    asm volatile("ldmatrix.sync.aligned.m8n8.x4.shared.b16 {%0,%1,%2,%3}, [%4];" \
                 : "=r"(r0), "=r"(r1), "=r"(r2), "=r"(r3) : "r"(addr))

#define MMA16816(d, a0, a1, a2, a3, b0, b1)                                      \
    asm volatile("mma.sync.aligned.m16n8k16.row.col.f32.f16.f16.f32 "            \
                 "{%0,%1,%2,%3},{%4,%5,%6,%7},{%8,%9},{%0,%1,%2,%3};"            \
                 : "+f"((d)[0]), "+f"((d)[1]), "+f"((d)[2]), "+f"((d)[3])        \
                 : "r"(a0), "r"(a1), "r"(a2), "r"(a3), "r"(b0), "r"(b1))

__global__ void __launch_bounds__(THREADS, 4)
encoder_kernel(const float* __restrict__ x,       // [B, T]
               const float* __restrict__ conv_w,  // [128, 1, 5]
               const float* __restrict__ conv_b,  // [128]
               const float* __restrict__ lin_w,   // [64, 128]
               const float* __restrict__ lin_b,   // [64]
               float* __restrict__ out)           // [B, S, 64]
{
    extern __shared__ char smem[];
    float*  xs  = (float*)(smem + SMEM_XS);
    float*  lb  = (float*)(smem + SMEM_LB);
    __half* fhi = (__half*)(smem + SMEM_FHI);
    __half* whi = (__half*)(smem + SMEM_WHI);

    const int tid  = threadIdx.x;
    const int wid  = tid >> 5;
    const int lane = tid & 31;
    const int b    = blockIdx.y;
    const int s0   = blockIdx.x * S_TILE;

    // ---- stage: input window, bias, fp16 linear weights ----
    {
        const long t0 = 2L * s0 - 2;
        const float* xb = x + (long)b * Tn;
        for (int i = tid; i < 2 * S_TILE + 3; i += THREADS) {
            long t = t0 + i;
            xs[i] = (t >= 0 && t < Tn) ? xb[t] : 0.f;
        }
        if (tid < Pn) lb[tid] = lin_b[tid];
        for (int i = tid; i < Pn * (En / 2); i += THREADS) {  // half2 pairs
            int p = i >> 6, e2 = i & 63;
            float2 w = *reinterpret_cast<const float2*>(lin_w + p * En + 2 * e2);
            *reinterpret_cast<__half2*>(whi + p * LDW + 2 * e2) =
                __halves2half2(__float2half_rn(w.x), __float2half_rn(w.y));
        }
    }

    // ---- conv taps: 4 channels per lane (vectorized loads) ----
    const int c0 = 4 * lane;        // channels c0..c0+3
    const int pb = wid * 16;        // 16 positions per thread
    float w[4][5], cb[4];
    {
        const float4* cw4 = reinterpret_cast<const float4*>(conv_w + 5 * c0);
        float4 q0 = cw4[0], q1 = cw4[1], q2 = cw4[2], q3 = cw4[3], q4 = cw4[4];
        w[0][0]=q0.x; w[0][1]=q0.y; w[0][2]=q0.z; w[0][3]=q0.w; w[0][4]=q1.x;
        w[1][0]=q1.y; w[1][1]=q1.z; w[1][2]=q1.w; w[1][3]=q2.x; w[1][4]=q2.y;
        w[2][0]=q2.z; w[2][1]=q2.w; w[2][2]=q3.x; w[2][3]=q3.y; w[2][4]=q3.z;
        w[3][0]=q3.w; w[3][1]=q4.x; w[3][2]=q4.y; w[3][3]=q4.z; w[3][4]=q4.w;
        float4 bb = *reinterpret_cast<const float4*>(conv_b + c0);
        cb[0]=bb.x; cb[1]=bb.y; cb[2]=bb.z; cb[3]=bb.w;
    }

    __syncthreads();   // xs staged

    // ---- conv1d + ReLU + fp16 -> padded A tile (STS.64) ----
    {
        const float* xw = xs + 2 * pb;   // broadcast reads within warp
        float x0 = xw[0], x1 = xw[1], x2 = xw[2], x3 = xw[3], x4 = xw[4];
#pragma unroll
        for (int p = 0; p < 16; p++) {
            __half2 vh[2];
#pragma unroll
            for (int j = 0; j < 2; j++) {
                float f0 = fmaf(w[2*j][0], x0, cb[2*j]);
                f0 = fmaf(w[2*j][1], x1, f0);
                f0 = fmaf(w[2*j][2], x2, f0);
                f0 = fmaf(w[2*j][3], x3, f0);
                f0 = fmaf(w[2*j][4], x4, f0);
                f0 = fmaxf(f0, 0.f);
                float f1 = fmaf(w[2*j+1][0], x0, cb[2*j+1]);
                f1 = fmaf(w[2*j+1][1], x1, f1);
                f1 = fmaf(w[2*j+1][2], x2, f1);
                f1 = fmaf(w[2*j+1][3], x3, f1);
                f1 = fmaf(w[2*j+1][4], x4, f1);
                f1 = fmaxf(f1, 0.f);
                vh[j] = __halves2half2(__float2half_rn(f0), __float2half_rn(f1));
            }
            *reinterpret_cast<uint2*>(fhi + (pb + p) * LDA + c0) =
                *reinterpret_cast<const uint2*>(vh);
            if (p < 15) {
                x0 = x2; x1 = x3; x2 = x4;
                x3 = xw[2 * p + 5]; x4 = xw[2 * p + 6];
            }
        }
    }
    __syncthreads();

    // ---- GEMM: 8 warps tiled 4m x 2n, each m32 x n32, single fp16 pass ----
    const int m0 = (wid & 3) * 32;
    const int n0 = (wid >> 2) * 32;

    float acc[2][4][4];
#pragma unroll
    for (int mt = 0; mt < 2; mt++)
#pragma unroll
        for (int nt = 0; nt < 4; nt++)
#pragma unroll
            for (int q = 0; q < 4; q++) acc[mt][nt][q] = 0.f;

    const int aoff0 = (m0 + (lane & 15)) * LDA + ((lane >> 4) << 3);
    const int aoff1 = aoff0 + 16 * LDA;
    const int brow  = (lane & 7) + ((lane >> 4) << 3);
    const int bcol  = ((lane >> 3) & 1) << 3;
    const int boff0 = (n0 + brow) * LDW + bcol;
    const int boff1 = boff0 + 16 * LDW;

    const uint32_t a_s0 = smem_u32(fhi + aoff0), a_s1 = smem_u32(fhi + aoff1);
    const uint32_t b_s0 = smem_u32(whi + boff0), b_s1 = smem_u32(whi + boff1);

#pragma unroll
    for (int c = 0; c < 8; c++) {
        const uint32_t kB = c * 32;  // k16 chunk byte offset

        uint32_t ah[2][4], bh[2][4];
        LDSM_X4(ah[0][0], ah[0][1], ah[0][2], ah[0][3], a_s0 + kB);
        LDSM_X4(ah[1][0], ah[1][1], ah[1][2], ah[1][3], a_s1 + kB);
        LDSM_X4(bh[0][0], bh[0][1], bh[0][2], bh[0][3], b_s0 + kB);
        LDSM_X4(bh[1][0], bh[1][1], bh[1][2], bh[1][3], b_s1 + kB);

#pragma unroll
        for (int mt = 0; mt < 2; mt++) {
#pragma unroll
            for (int np = 0; np < 2; np++) {
                MMA16816(acc[mt][2*np+0], ah[mt][0], ah[mt][1], ah[mt][2], ah[mt][3],
                         bh[np][0], bh[np][1]);
                MMA16816(acc[mt][2*np+1], ah[mt][0], ah[mt][1], ah[mt][2], ah[mt][3],
                         bh[np][2], bh[np][3]);
            }
        }
    }

    // ---- epilogue: bias + float2 stores ----
    const int gid = lane >> 2, tig = lane & 3;
#pragma unroll
    for (int mt = 0; mt < 2; mt++) {
        const int row = s0 + m0 + mt * 16 + gid;
        float* ob = out + ((long)b * Sn + row) * Pn;
#pragma unroll
        for (int nt = 0; nt < 4; nt++) {
            const int col = n0 + nt * 8 + tig * 2;
            const float bb0 = lb[col], bb1 = lb[col + 1];
            float2 v0 = make_float2(acc[mt][nt][0] + bb0, acc[mt][nt][1] + bb1);
            float2 v1 = make_float2(acc[mt][nt][2] + bb0, acc[mt][nt][3] + bb1);
            *reinterpret_cast<float2*>(ob + col) = v0;
            *reinterpret_cast<float2*>(ob + 8 * Pn + col) = v1;
        }
    }
}

extern "C" void kernel_launch(void* const* d_in, const int* in_sizes, int n_in,
                              void* d_out, int out_size) {
    (void)in_sizes; (void)n_in; (void)out_size;
    const float* x      = (const float*)d_in[0];
    const float* conv_w = (const float*)d_in[1];
    const float* conv_b = (const float*)d_in[2];
    const float* lin_w  = (const float*)d_in[3];
    const float* lin_b  = (const float*)d_in[4];
    float* out = (float*)d_out;

    cudaFuncSetAttribute(encoder_kernel,
                         cudaFuncAttributeMaxDynamicSharedMemorySize, SMEM_TOTAL);

    dim3 grid((unsigned)(Sn / S_TILE), Bn);
    encoder_kernel<<<grid, THREADS, SMEM_TOTAL>>>(x, conv_w, conv_b, lin_w, lin_b, out);
}

// round 6
// speedup vs baseline: 2.7508x; 1.1526x over previous
#include <cuda_runtime.h>
#include <cuda_fp16.h>
#include <cstdint>

namespace {
constexpr int  Bn = 8;
constexpr long Tn = 262144;
constexpr long Sn = 131072;   // output positions
constexpr int  En = 128;      // conv channels = GEMM K
constexpr int  Pn = 64;       // out features  = GEMM N
constexpr int  S_TILE = 128;  // GEMM M per CTA
constexpr int  THREADS = 256;
constexpr int  LDA = 136;     // halves/row, padded -> conflict-free ldmatrix

constexpr int SMEM_TOTAL = S_TILE * LDA * 2;   // 34816 B (A tile only)
}

// B fragments in MMA register order: [ngroup(2)][chunk(8)][lane(32)][2 x uint4]
__device__ uint4 g_bfrag[2 * 8 * 32 * 2];

__device__ __forceinline__ uint32_t smem_u32(const void* p) {
    return (uint32_t)__cvta_generic_to_shared(p);
}

#define LDSM_X4(r0, r1, r2, r3, addr)                                            \
    asm volatile("ldmatrix.sync.aligned.m8n8.x4.shared.b16 {%0,%1,%2,%3}, [%4];" \
                 : "=r"(r0), "=r"(r1), "=r"(r2), "=r"(r3) : "r"(addr))

#define MMA16816(d, a0, a1, a2, a3, b0, b1)                                      \
    asm volatile("mma.sync.aligned.m16n8k16.row.col.f32.f16.f16.f32 "            \
                 "{%0,%1,%2,%3},{%4,%5,%6,%7},{%8,%9},{%0,%1,%2,%3};"            \
                 : "+f"((d)[0]), "+f"((d)[1]), "+f"((d)[2]), "+f"((d)[3])        \
                 : "r"(a0), "r"(a1), "r"(a2), "r"(a3), "r"(b0), "r"(b1))

// ---- init: pack lin_w (fp32 [64,128]) into fp16 B fragments ----
__global__ void pack_w_kernel(const float* __restrict__ lin_w) {
    const int idx = blockIdx.x * blockDim.x + threadIdx.x;   // 512 threads
    if (idx >= 2 * 8 * 32) return;
    const int lane  = idx & 31;
    const int chunk = (idx >> 5) & 7;
    const int G     = idx >> 8;

    uint32_t r[8];
#pragma unroll
    for (int s = 0; s < 2; s++) {
#pragma unroll
        for (int q = 0; q < 4; q++) {
            const int n = 32 * G + 16 * s + ((q >> 1) << 3) + (lane >> 2);
            const int k = 16 * chunk + ((q & 1) << 3) + ((lane & 3) << 1);
            const float2 w = *reinterpret_cast<const float2*>(lin_w + n * En + k);
            __half2 h = __halves2half2(__float2half_rn(w.x), __float2half_rn(w.y));
            r[s * 4 + q] = *reinterpret_cast<const uint32_t*>(&h);
        }
    }
    uint4* dst = g_bfrag + 2 * idx;
    dst[0] = make_uint4(r[0], r[1], r[2], r[3]);
    dst[1] = make_uint4(r[4], r[5], r[6], r[7]);
}

__global__ void __launch_bounds__(THREADS, 4)
encoder_kernel(const float* __restrict__ x,       // [B, T]
               const float* __restrict__ conv_w,  // [128, 1, 5]
               const float* __restrict__ conv_b,  // [128]
               const float* __restrict__ lin_b,   // [64]
               float* __restrict__ out)           // [B, S, 64]
{
    extern __shared__ char smem[];
    __half* fhi = (__half*)smem;

    const int tid  = threadIdx.x;
    const int wid  = tid >> 5;
    const int lane = tid & 31;
    const int b    = blockIdx.y;
    const int s0   = blockIdx.x * S_TILE;

    // ---- conv taps: 4 channels per lane (vectorized loads) ----
    const int c0 = 4 * lane;        // channels c0..c0+3
    const int pb = wid * 16;        // 16 positions per warp
    float w[4][5], cb[4];
    {
        const float4* cw4 = reinterpret_cast<const float4*>(conv_w + 5 * c0);
        float4 q0 = cw4[0], q1 = cw4[1], q2 = cw4[2], q3 = cw4[3], q4 = cw4[4];
        w[0][0]=q0.x; w[0][1]=q0.y; w[0][2]=q0.z; w[0][3]=q0.w; w[0][4]=q1.x;
        w[1][0]=q1.y; w[1][1]=q1.z; w[1][2]=q1.w; w[1][3]=q2.x; w[1][4]=q2.y;
        w[2][0]=q2.z; w[2][1]=q2.w; w[2][2]=q3.x; w[2][3]=q3.y; w[2][4]=q3.z;
        w[3][0]=q3.w; w[3][1]=q4.x; w[3][2]=q4.y; w[3][3]=q4.z; w[3][4]=q4.w;
        float4 bb = *reinterpret_cast<const float4*>(conv_b + c0);
        cb[0]=bb.x; cb[1]=bb.y; cb[2]=bb.z; cb[3]=bb.w;
    }

    // ---- warp-private input window in registers (35 floats across lanes) ----
    const long t0w = 2L * (s0 + pb) - 2;
    float xv0, xv1;
    {
        const float* xb = x + (long)b * Tn;
        long t = t0w + lane;
        xv0 = (t >= 0 && t < Tn) ? xb[t] : 0.f;
        t += 32;
        xv1 = (t >= 0 && t < Tn) ? xb[t] : 0.f;
    }

    // ---- conv1d + ReLU + fp16 -> padded A tile (STS.64), shfl-broadcast x ----
    {
        const unsigned m = 0xFFFFFFFFu;
        float x0 = __shfl_sync(m, xv0, 0), x1 = __shfl_sync(m, xv0, 1),
              x2 = __shfl_sync(m, xv0, 2), x3 = __shfl_sync(m, xv0, 3),
              x4 = __shfl_sync(m, xv0, 4);
#pragma unroll
        for (int p = 0; p < 16; p++) {
            __half2 vh[2];
#pragma unroll
            for (int j = 0; j < 2; j++) {
                float f0 = fmaf(w[2*j][0], x0, cb[2*j]);
                f0 = fmaf(w[2*j][1], x1, f0);
                f0 = fmaf(w[2*j][2], x2, f0);
                f0 = fmaf(w[2*j][3], x3, f0);
                f0 = fmaf(w[2*j][4], x4, f0);
                f0 = fmaxf(f0, 0.f);
                float f1 = fmaf(w[2*j+1][0], x0, cb[2*j+1]);
                f1 = fmaf(w[2*j+1][1], x1, f1);
                f1 = fmaf(w[2*j+1][2], x2, f1);
                f1 = fmaf(w[2*j+1][3], x3, f1);
                f1 = fmaf(w[2*j+1][4], x4, f1);
                f1 = fmaxf(f1, 0.f);
                vh[j] = __halves2half2(__float2half_rn(f0), __float2half_rn(f1));
            }
            *reinterpret_cast<uint2*>(fhi + (pb + p) * LDA + c0) =
                *reinterpret_cast<const uint2*>(vh);
            if (p < 15) {
                x0 = x2; x1 = x3; x2 = x4;
                const int i5 = 2 * p + 5, i6 = 2 * p + 6;   // compile-time consts
                x3 = (i5 < 32) ? __shfl_sync(m, xv0, i5) : __shfl_sync(m, xv1, i5 - 32);
                x4 = (i6 < 32) ? __shfl_sync(m, xv0, i6) : __shfl_sync(m, xv1, i6 - 32);
            }
        }
    }
    __syncthreads();

    // ---- GEMM: 8 warps tiled 4m x 2n, each m32 x n32 ----
    const int m0 = (wid & 3) * 32;
    const int G  = wid >> 2;          // n-group: n0 = 32*G

    float acc[2][4][4];
#pragma unroll
    for (int mt = 0; mt < 2; mt++)
#pragma unroll
        for (int nt = 0; nt < 4; nt++)
#pragma unroll
            for (int q = 0; q < 4; q++) acc[mt][nt][q] = 0.f;

    const int aoff0 = (m0 + (lane & 15)) * LDA + ((lane >> 4) << 3);
    const uint32_t a_s0 = smem_u32(fhi + aoff0);
    const uint32_t a_s1 = smem_u32(fhi + aoff0 + 16 * LDA);
    const uint4* bp = g_bfrag + 2 * ((G * 8) * 32 + lane);   // + chunk*64

#pragma unroll
    for (int c = 0; c < 8; c++) {
        const uint32_t kB = c * 32;

        uint32_t ah[2][4];
        LDSM_X4(ah[0][0], ah[0][1], ah[0][2], ah[0][3], a_s0 + kB);
        LDSM_X4(ah[1][0], ah[1][1], ah[1][2], ah[1][3], a_s1 + kB);
        const uint4 v0 = bp[c * 64 + 0];
        const uint4 v1 = bp[c * 64 + 1];
        const uint32_t bh[2][4] = {{v0.x, v0.y, v0.z, v0.w},
                                   {v1.x, v1.y, v1.z, v1.w}};

#pragma unroll
        for (int mt = 0; mt < 2; mt++) {
#pragma unroll
            for (int np = 0; np < 2; np++) {
                MMA16816(acc[mt][2*np+0], ah[mt][0], ah[mt][1], ah[mt][2], ah[mt][3],
                         bh[np][0], bh[np][1]);
                MMA16816(acc[mt][2*np+1], ah[mt][0], ah[mt][1], ah[mt][2], ah[mt][3],
                         bh[np][2], bh[np][3]);
            }
        }
    }

    // ---- epilogue: bias (L1-cached LDG) + float2 stores ----
    const int gid = lane >> 2, tig = lane & 3;
    float bb[4][2];
#pragma unroll
    for (int nt = 0; nt < 4; nt++) {
        const int col = 32 * G + nt * 8 + tig * 2;
        const float2 v = __ldg(reinterpret_cast<const float2*>(lin_b + col));
        bb[nt][0] = v.x; bb[nt][1] = v.y;
    }
#pragma unroll
    for (int mt = 0; mt < 2; mt++) {
        const int row = s0 + m0 + mt * 16 + gid;
        float* ob = out + ((long)b * Sn + row) * Pn;
#pragma unroll
        for (int nt = 0; nt < 4; nt++) {
            const int col = 32 * G + nt * 8 + tig * 2;
            float2 v0 = make_float2(acc[mt][nt][0] + bb[nt][0], acc[mt][nt][1] + bb[nt][1]);
            float2 v1 = make_float2(acc[mt][nt][2] + bb[nt][0], acc[mt][nt][3] + bb[nt][1]);
            *reinterpret_cast<float2*>(ob + col) = v0;
            *reinterpret_cast<float2*>(ob + 8 * Pn + col) = v1;
        }
    }
}

extern "C" void kernel_launch(void* const* d_in, const int* in_sizes, int n_in,
                              void* d_out, int out_size) {
    (void)in_sizes; (void)n_in; (void)out_size;
    const float* x      = (const float*)d_in[0];
    const float* conv_w = (const float*)d_in[1];
    const float* conv_b = (const float*)d_in[2];
    const float* lin_w  = (const float*)d_in[3];
    const float* lin_b  = (const float*)d_in[4];
    float* out = (float*)d_out;

    pack_w_kernel<<<2, 256>>>(lin_w);

    cudaFuncSetAttribute(encoder_kernel,
                         cudaFuncAttributeMaxDynamicSharedMemorySize, SMEM_TOTAL);
    dim3 grid((unsigned)(Sn / S_TILE), Bn);
    encoder_kernel<<<grid, THREADS, SMEM_TOTAL>>>(x, conv_w, conv_b, lin_b, out);
}

// round 7
// speedup vs baseline: 3.0626x; 1.1133x over previous
#include <cuda_runtime.h>
#include <cuda_fp16.h>
#include <cstdint>

namespace {
constexpr int  Bn = 8;
constexpr long Tn = 262144;
constexpr long Sn = 131072;   // output positions
constexpr int  En = 128;      // conv channels = GEMM K
constexpr int  Pn = 64;       // out features  = GEMM N
constexpr int  S_TILE = 128;  // GEMM M per CTA
constexpr int  THREADS = 256;
constexpr int  LDA = 136;     // halves/row, padded -> conflict-free ldmatrix

constexpr int SMEM_TOTAL = S_TILE * LDA * 2;   // 34816 B (A tile only)
}

// B fragments, lane-contiguous: [G(2)][chunk(8)][pair(2)][lane(32)] of uint4
__device__ uint4 g_bfrag[2 * 8 * 2 * 32];

__device__ __forceinline__ uint32_t smem_u32(const void* p) {
    return (uint32_t)__cvta_generic_to_shared(p);
}

#define LDSM_X4(r0, r1, r2, r3, addr)                                            \
    asm volatile("ldmatrix.sync.aligned.m8n8.x4.shared.b16 {%0,%1,%2,%3}, [%4];" \
                 : "=r"(r0), "=r"(r1), "=r"(r2), "=r"(r3) : "r"(addr))

#define MMA16816(d, a0, a1, a2, a3, b0, b1)                                      \
    asm volatile("mma.sync.aligned.m16n8k16.row.col.f32.f16.f16.f32 "            \
                 "{%0,%1,%2,%3},{%4,%5,%6,%7},{%8,%9},{%0,%1,%2,%3};"            \
                 : "+f"((d)[0]), "+f"((d)[1]), "+f"((d)[2]), "+f"((d)[3])        \
                 : "r"(a0), "r"(a1), "r"(a2), "r"(a3), "r"(b0), "r"(b1))

// ---- init: pack lin_w (fp32 [64,128]) into fp16 B fragments ----
// N-permutation: fragment (tile nt, within-tile n = vn) -> logical col
//   n_log = 32*G + (vn>>1)*8 + nt*2 + (vn&1)
// so that D-fragment thread (tig) owns 8 CONSECUTIVE logical cols per row.
__global__ void pack_w_kernel(const float* __restrict__ lin_w) {
    const int idx = blockIdx.x * blockDim.x + threadIdx.x;   // 512 threads
    if (idx >= 2 * 8 * 32) return;
    const int lane  = idx & 31;
    const int chunk = (idx >> 5) & 7;
    const int G     = idx >> 8;

    uint32_t r[8];
#pragma unroll
    for (int s = 0; s < 2; s++) {          // reg pair (np)
#pragma unroll
        for (int q = 0; q < 4; q++) {
            const int nt = 2 * s + (q >> 1);                 // n8 tile index 0..3
            const int n  = 32 * G + (lane >> 3) * 8 + nt * 2 + ((lane >> 2) & 1);
            const int k  = 16 * chunk + ((q & 1) << 3) + ((lane & 3) << 1);
            const float2 w = *reinterpret_cast<const float2*>(lin_w + n * En + k);
            __half2 h = __halves2half2(__float2half_rn(w.x), __float2half_rn(w.y));
            r[s * 4 + q] = *reinterpret_cast<const uint32_t*>(&h);
        }
    }
    g_bfrag[((G * 8 + chunk) * 2 + 0) * 32 + lane] = make_uint4(r[0], r[1], r[2], r[3]);
    g_bfrag[((G * 8 + chunk) * 2 + 1) * 32 + lane] = make_uint4(r[4], r[5], r[6], r[7]);
}

__global__ void __launch_bounds__(THREADS, 4)
encoder_kernel(const float* __restrict__ x,       // [B, T]
               const float* __restrict__ conv_w,  // [128, 1, 5]
               const float* __restrict__ conv_b,  // [128]
               const float* __restrict__ lin_b,   // [64]
               float* __restrict__ out)           // [B, S, 64]
{
    extern __shared__ char smem[];
    __half* fhi = (__half*)smem;

    const int tid  = threadIdx.x;
    const int wid  = tid >> 5;
    const int lane = tid & 31;
    const int b    = blockIdx.y;
    const int s0   = blockIdx.x * S_TILE;

    // ---- conv taps: 4 channels per lane (vectorized loads) ----
    const int c0 = 4 * lane;        // channels c0..c0+3
    const int pb = wid * 16;        // 16 positions per warp
    float w[4][5], cb[4];
    {
        const float4* cw4 = reinterpret_cast<const float4*>(conv_w + 5 * c0);
        float4 q0 = cw4[0], q1 = cw4[1], q2 = cw4[2], q3 = cw4[3], q4 = cw4[4];
        w[0][0]=q0.x; w[0][1]=q0.y; w[0][2]=q0.z; w[0][3]=q0.w; w[0][4]=q1.x;
        w[1][0]=q1.y; w[1][1]=q1.z; w[1][2]=q1.w; w[1][3]=q2.x; w[1][4]=q2.y;
        w[2][0]=q2.z; w[2][1]=q2.w; w[2][2]=q3.x; w[2][3]=q3.y; w[2][4]=q3.z;
        w[3][0]=q3.w; w[3][1]=q4.x; w[3][2]=q4.y; w[3][3]=q4.z; w[3][4]=q4.w;
        float4 bb = *reinterpret_cast<const float4*>(conv_b + c0);
        cb[0]=bb.x; cb[1]=bb.y; cb[2]=bb.z; cb[3]=bb.w;
    }

    // ---- warp-private input window in registers (35 floats across lanes) ----
    const long t0w = 2L * (s0 + pb) - 2;
    float xv0, xv1;
    {
        const float* xb = x + (long)b * Tn;
        long t = t0w + lane;
        xv0 = (t >= 0 && t < Tn) ? xb[t] : 0.f;
        t += 32;
        xv1 = (t >= 0 && t < Tn) ? xb[t] : 0.f;
    }

    // ---- conv1d + ReLU + fp16 -> padded A tile (STS.64), shfl-broadcast x ----
    {
        const unsigned m = 0xFFFFFFFFu;
        float x0 = __shfl_sync(m, xv0, 0), x1 = __shfl_sync(m, xv0, 1),
              x2 = __shfl_sync(m, xv0, 2), x3 = __shfl_sync(m, xv0, 3),
              x4 = __shfl_sync(m, xv0, 4);
#pragma unroll
        for (int p = 0; p < 16; p++) {
            __half2 vh[2];
#pragma unroll
            for (int j = 0; j < 2; j++) {
                float f0 = fmaf(w[2*j][0], x0, cb[2*j]);
                f0 = fmaf(w[2*j][1], x1, f0);
                f0 = fmaf(w[2*j][2], x2, f0);
                f0 = fmaf(w[2*j][3], x3, f0);
                f0 = fmaf(w[2*j][4], x4, f0);
                f0 = fmaxf(f0, 0.f);
                float f1 = fmaf(w[2*j+1][0], x0, cb[2*j+1]);
                f1 = fmaf(w[2*j+1][1], x1, f1);
                f1 = fmaf(w[2*j+1][2], x2, f1);
                f1 = fmaf(w[2*j+1][3], x3, f1);
                f1 = fmaf(w[2*j+1][4], x4, f1);
                f1 = fmaxf(f1, 0.f);
                vh[j] = __halves2half2(__float2half_rn(f0), __float2half_rn(f1));
            }
            *reinterpret_cast<uint2*>(fhi + (pb + p) * LDA + c0) =
                *reinterpret_cast<const uint2*>(vh);
            if (p < 15) {
                x0 = x2; x1 = x3; x2 = x4;
                const int i5 = 2 * p + 5, i6 = 2 * p + 6;   // compile-time consts
                x3 = (i5 < 32) ? __shfl_sync(m, xv0, i5) : __shfl_sync(m, xv1, i5 - 32);
                x4 = (i6 < 32) ? __shfl_sync(m, xv0, i6) : __shfl_sync(m, xv1, i6 - 32);
            }
        }
    }
    __syncthreads();

    // ---- GEMM: 8 warps tiled 4m x 2n, each m32 x n32 ----
    const int m0 = (wid & 3) * 32;
    const int G  = wid >> 2;          // n-group: logical cols 32*G..32*G+31

    float acc[2][4][4];
#pragma unroll
    for (int mt = 0; mt < 2; mt++)
#pragma unroll
        for (int nt = 0; nt < 4; nt++)
#pragma unroll
            for (int q = 0; q < 4; q++) acc[mt][nt][q] = 0.f;

    const int aoff0 = (m0 + (lane & 15)) * LDA + ((lane >> 4) << 3);
    const uint32_t a_s0 = smem_u32(fhi + aoff0);
    const uint32_t a_s1 = smem_u32(fhi + aoff0 + 16 * LDA);
    const uint4* bp = g_bfrag + (G * 8) * 2 * 32 + lane;   // + (chunk*2 + pair)*32

#pragma unroll
    for (int c = 0; c < 8; c++) {
        const uint32_t kB = c * 32;

        uint32_t ah[2][4];
        LDSM_X4(ah[0][0], ah[0][1], ah[0][2], ah[0][3], a_s0 + kB);
        LDSM_X4(ah[1][0], ah[1][1], ah[1][2], ah[1][3], a_s1 + kB);
        const uint4 v0 = __ldg(bp + c * 64);
        const uint4 v1 = __ldg(bp + c * 64 + 32);
        const uint32_t bh[2][4] = {{v0.x, v0.y, v0.z, v0.w},
                                   {v1.x, v1.y, v1.z, v1.w}};

#pragma unroll
        for (int mt = 0; mt < 2; mt++) {
#pragma unroll
            for (int np = 0; np < 2; np++) {
                MMA16816(acc[mt][2*np+0], ah[mt][0], ah[mt][1], ah[mt][2], ah[mt][3],
                         bh[np][0], bh[np][1]);
                MMA16816(acc[mt][2*np+1], ah[mt][0], ah[mt][1], ah[mt][2], ah[mt][3],
                         bh[np][2], bh[np][3]);
            }
        }
    }

    // ---- epilogue: each thread owns 8 consecutive cols per row -> STG.128 ----
    const int gid = lane >> 2, tig = lane & 3;
    const int colb = 32 * G + tig * 8;
    float bb[8];
    {
        const float4 b0 = __ldg(reinterpret_cast<const float4*>(lin_b + colb));
        const float4 b1 = __ldg(reinterpret_cast<const float4*>(lin_b + colb + 4));
        bb[0]=b0.x; bb[1]=b0.y; bb[2]=b0.z; bb[3]=b0.w;
        bb[4]=b1.x; bb[5]=b1.y; bb[6]=b1.z; bb[7]=b1.w;
    }
#pragma unroll
    for (int mt = 0; mt < 2; mt++) {
        const int row = s0 + m0 + mt * 16 + gid;
        float* ob = out + ((long)b * Sn + row) * Pn + colb;
        // row gid: acc[mt][nt][0..1] ; row gid+8: acc[mt][nt][2..3]
        float4 r0a = make_float4(acc[mt][0][0]+bb[0], acc[mt][0][1]+bb[1],
                                 acc[mt][1][0]+bb[2], acc[mt][1][1]+bb[3]);
        float4 r0b = make_float4(acc[mt][2][0]+bb[4], acc[mt][2][1]+bb[5],
                                 acc[mt][3][0]+bb[6], acc[mt][3][1]+bb[7]);
        float4 r1a = make_float4(acc[mt][0][2]+bb[0], acc[mt][0][3]+bb[1],
                                 acc[mt][1][2]+bb[2], acc[mt][1][3]+bb[3]);
        float4 r1b = make_float4(acc[mt][2][2]+bb[4], acc[mt][2][3]+bb[5],
                                 acc[mt][3][2]+bb[6], acc[mt][3][3]+bb[7]);
        *reinterpret_cast<float4*>(ob)            = r0a;
        *reinterpret_cast<float4*>(ob + 4)        = r0b;
        *reinterpret_cast<float4*>(ob + 8 * Pn)     = r1a;
        *reinterpret_cast<float4*>(ob + 8 * Pn + 4) = r1b;
    }
}

extern "C" void kernel_launch(void* const* d_in, const int* in_sizes, int n_in,
                              void* d_out, int out_size) {
    (void)in_sizes; (void)n_in; (void)out_size;
    const float* x      = (const float*)d_in[0];
    const float* conv_w = (const float*)d_in[1];
    const float* conv_b = (const float*)d_in[2];
    const float* lin_w  = (const float*)d_in[3];
    const float* lin_b  = (const float*)d_in[4];
    float* out = (float*)d_out;

    pack_w_kernel<<<2, 256>>>(lin_w);

    cudaFuncSetAttribute(encoder_kernel,
                         cudaFuncAttributeMaxDynamicSharedMemorySize, SMEM_TOTAL);
    dim3 grid((unsigned)(Sn / S_TILE), Bn);
    encoder_kernel<<<grid, THREADS, SMEM_TOTAL>>>(x, conv_w, conv_b, lin_b, out);
}

// round 8
// speedup vs baseline: 3.1730x; 1.0360x over previous
#include <cuda_runtime.h>
#include <cuda_fp16.h>
#include <cstdint>

namespace {
constexpr int  Bn = 8;
constexpr long Tn = 262144;
constexpr long Sn = 131072;   // output positions
constexpr int  En = 128;      // conv channels = GEMM K
constexpr int  Pn = 64;       // out features  = GEMM N
constexpr int  S_TILE = 128;  // GEMM M per CTA
constexpr int  THREADS = 256;
constexpr int  LDA = 136;     // halves/row, padded -> conflict-free ldmatrix

constexpr int SMEM_TOTAL = S_TILE * LDA * 2;   // 34816 B (A tile only)
}

// B fragments, lane-contiguous: [G(2)][chunk(8)][pair(2)][lane(32)] of uint4
__device__ uint4 g_bfrag[2 * 8 * 2 * 32];

__device__ __forceinline__ uint32_t smem_u32(const void* p) {
    return (uint32_t)__cvta_generic_to_shared(p);
}

#define LDSM_X4(r0, r1, r2, r3, addr)                                            \
    asm volatile("ldmatrix.sync.aligned.m8n8.x4.shared.b16 {%0,%1,%2,%3}, [%4];" \
                 : "=r"(r0), "=r"(r1), "=r"(r2), "=r"(r3) : "r"(addr))

#define MMA16816(d, a0, a1, a2, a3, b0, b1)                                      \
    asm volatile("mma.sync.aligned.m16n8k16.row.col.f32.f16.f16.f32 "            \
                 "{%0,%1,%2,%3},{%4,%5,%6,%7},{%8,%9},{%0,%1,%2,%3};"            \
                 : "+f"((d)[0]), "+f"((d)[1]), "+f"((d)[2]), "+f"((d)[3])        \
                 : "r"(a0), "r"(a1), "r"(a2), "r"(a3), "r"(b0), "r"(b1))

// ---- init: pack lin_w (fp32 [64,128]) into fp16 B fragments ----
// N-permutation: logical col = 32*G + (vn>>1)*8 + nt*2 + (vn&1) so each
// D-fragment thread owns 8 consecutive output columns per row.
__global__ void pack_w_kernel(const float* __restrict__ lin_w) {
    const int idx = blockIdx.x * blockDim.x + threadIdx.x;   // 512 threads
    if (idx >= 2 * 8 * 32) return;
    const int lane  = idx & 31;
    const int chunk = (idx >> 5) & 7;
    const int G     = idx >> 8;

    uint32_t r[8];
#pragma unroll
    for (int s = 0; s < 2; s++) {          // reg pair (np)
#pragma unroll
        for (int q = 0; q < 4; q++) {
            const int nt = 2 * s + (q >> 1);                 // n8 tile index 0..3
            const int n  = 32 * G + (lane >> 3) * 8 + nt * 2 + ((lane >> 2) & 1);
            const int k  = 16 * chunk + ((q & 1) << 3) + ((lane & 3) << 1);
            const float2 w = *reinterpret_cast<const float2*>(lin_w + n * En + k);
            __half2 h = __halves2half2(__float2half_rn(w.x), __float2half_rn(w.y));
            r[s * 4 + q] = *reinterpret_cast<const uint32_t*>(&h);
        }
    }
    g_bfrag[((G * 8 + chunk) * 2 + 0) * 32 + lane] = make_uint4(r[0], r[1], r[2], r[3]);
    g_bfrag[((G * 8 + chunk) * 2 + 1) * 32 + lane] = make_uint4(r[4], r[5], r[6], r[7]);
}

__global__ void __launch_bounds__(THREADS, 4)
encoder_kernel(const float* __restrict__ x,       // [B, T]
               const float* __restrict__ conv_w,  // [128, 1, 5]
               const float* __restrict__ conv_b,  // [128]
               const float* __restrict__ lin_b,   // [64]
               float* __restrict__ out)           // [B, S, 64]
{
    extern __shared__ char smem[];
    __half* fhi = (__half*)smem;

    const int tid  = threadIdx.x;
    const int wid  = tid >> 5;
    const int lane = tid & 31;
    const int b    = blockIdx.y;
    const int s0   = blockIdx.x * S_TILE;
    const int q    = wid & 3;        // pipeline group: warps {q, q+4}

    // ---- conv taps: 4 channels per lane (vectorized loads) ----
    const int c0 = 4 * lane;                       // channels c0..c0+3
    const int pb = 32 * q + 16 * (wid >> 2);       // 16 rows, paired with warp wid^4
    float w[4][5], cb[4];
    {
        const float4* cw4 = reinterpret_cast<const float4*>(conv_w + 5 * c0);
        float4 q0 = cw4[0], q1 = cw4[1], q2 = cw4[2], q3 = cw4[3], q4 = cw4[4];
        w[0][0]=q0.x; w[0][1]=q0.y; w[0][2]=q0.z; w[0][3]=q0.w; w[0][4]=q1.x;
        w[1][0]=q1.y; w[1][1]=q1.z; w[1][2]=q1.w; w[1][3]=q2.x; w[1][4]=q2.y;
        w[2][0]=q2.z; w[2][1]=q2.w; w[2][2]=q3.x; w[2][3]=q3.y; w[2][4]=q3.z;
        w[3][0]=q3.w; w[3][1]=q4.x; w[3][2]=q4.y; w[3][3]=q4.z; w[3][4]=q4.w;
        float4 bb = *reinterpret_cast<const float4*>(conv_b + c0);
        cb[0]=bb.x; cb[1]=bb.y; cb[2]=bb.z; cb[3]=bb.w;
    }

    // ---- warp-private input window in registers (35 floats across lanes) ----
    const long t0w = 2L * (s0 + pb) - 2;
    float xv0, xv1;
    {
        const float* xb = x + (long)b * Tn;
        long t = t0w + lane;
        xv0 = (t >= 0 && t < Tn) ? xb[t] : 0.f;
        t += 32;
        xv1 = (t >= 0 && t < Tn) ? xb[t] : 0.f;
    }

    // ---- conv1d + ReLU + fp16 -> padded A tile rows pb..pb+15 ----
    {
        const unsigned m = 0xFFFFFFFFu;
        float x0 = __shfl_sync(m, xv0, 0), x1 = __shfl_sync(m, xv0, 1),
              x2 = __shfl_sync(m, xv0, 2), x3 = __shfl_sync(m, xv0, 3),
              x4 = __shfl_sync(m, xv0, 4);
#pragma unroll
        for (int p = 0; p < 16; p++) {
            __half2 vh[2];
#pragma unroll
            for (int j = 0; j < 2; j++) {
                float f0 = fmaf(w[2*j][0], x0, cb[2*j]);
                f0 = fmaf(w[2*j][1], x1, f0);
                f0 = fmaf(w[2*j][2], x2, f0);
                f0 = fmaf(w[2*j][3], x3, f0);
                f0 = fmaf(w[2*j][4], x4, f0);
                f0 = fmaxf(f0, 0.f);
                float f1 = fmaf(w[2*j+1][0], x0, cb[2*j+1]);
                f1 = fmaf(w[2*j+1][1], x1, f1);
                f1 = fmaf(w[2*j+1][2], x2, f1);
                f1 = fmaf(w[2*j+1][3], x3, f1);
                f1 = fmaf(w[2*j+1][4], x4, f1);
                f1 = fmaxf(f1, 0.f);
                vh[j] = __halves2half2(__float2half_rn(f0), __float2half_rn(f1));
            }
            *reinterpret_cast<uint2*>(fhi + (pb + p) * LDA + c0) =
                *reinterpret_cast<const uint2*>(vh);
            if (p < 15) {
                x0 = x2; x1 = x3; x2 = x4;
                const int i5 = 2 * p + 5, i6 = 2 * p + 6;   // compile-time consts
                x3 = (i5 < 32) ? __shfl_sync(m, xv0, i5) : __shfl_sync(m, xv1, i5 - 32);
                x4 = (i6 < 32) ? __shfl_sync(m, xv0, i6) : __shfl_sync(m, xv1, i6 - 32);
            }
        }
    }

    // pairwise producer/consumer barrier: warps {q, q+4} (drains STS)
    asm volatile("bar.sync %0, 64;" :: "r"(q) : "memory");

    // ---- GEMM: 8 warps tiled 4m x 2n, each m32 x n32 ----
    const int m0 = q * 32;
    const int G  = wid >> 2;          // n-group: logical cols 32*G..32*G+31

    float acc[2][4][4];
#pragma unroll
    for (int mt = 0; mt < 2; mt++)
#pragma unroll
        for (int nt = 0; nt < 4; nt++)
#pragma unroll
            for (int qq = 0; qq < 4; qq++) acc[mt][nt][qq] = 0.f;

    const int aoff0 = (m0 + (lane & 15)) * LDA + ((lane >> 4) << 3);
    const uint32_t a_s0 = smem_u32(fhi + aoff0);
    const uint32_t a_s1 = smem_u32(fhi + aoff0 + 16 * LDA);
    const uint4* bp = g_bfrag + (G * 8) * 2 * 32 + lane;   // + (chunk*2 + pair)*32

#pragma unroll
    for (int c = 0; c < 8; c++) {
        const uint32_t kB = c * 32;

        uint32_t ah[2][4];
        LDSM_X4(ah[0][0], ah[0][1], ah[0][2], ah[0][3], a_s0 + kB);
        LDSM_X4(ah[1][0], ah[1][1], ah[1][2], ah[1][3], a_s1 + kB);
        const uint4 v0 = __ldg(bp + c * 64);
        const uint4 v1 = __ldg(bp + c * 64 + 32);
        const uint32_t bh[2][4] = {{v0.x, v0.y, v0.z, v0.w},
                                   {v1.x, v1.y, v1.z, v1.w}};

#pragma unroll
        for (int mt = 0; mt < 2; mt++) {
#pragma unroll
            for (int np = 0; np < 2; np++) {
                MMA16816(acc[mt][2*np+0], ah[mt][0], ah[mt][1], ah[mt][2], ah[mt][3],
                         bh[np][0], bh[np][1]);
                MMA16816(acc[mt][2*np+1], ah[mt][0], ah[mt][1], ah[mt][2], ah[mt][3],
                         bh[np][2], bh[np][3]);
            }
        }
    }

    // ---- epilogue: each thread owns 8 consecutive cols per row -> STG.128 ----
    const int gid = lane >> 2, tig = lane & 3;
    const int colb = 32 * G + tig * 8;
    float bb[8];
    {
        const float4 b0 = __ldg(reinterpret_cast<const float4*>(lin_b + colb));
        const float4 b1 = __ldg(reinterpret_cast<const float4*>(lin_b + colb + 4));
        bb[0]=b0.x; bb[1]=b0.y; bb[2]=b0.z; bb[3]=b0.w;
        bb[4]=b1.x; bb[5]=b1.y; bb[6]=b1.z; bb[7]=b1.w;
    }
#pragma unroll
    for (int mt = 0; mt < 2; mt++) {
        const int row = s0 + m0 + mt * 16 + gid;
        float* ob = out + ((long)b * Sn + row) * Pn + colb;
        float4 r0a = make_float4(acc[mt][0][0]+bb[0], acc[mt][0][1]+bb[1],
                                 acc[mt][1][0]+bb[2], acc[mt][1][1]+bb[3]);
        float4 r0b = make_float4(acc[mt][2][0]+bb[4], acc[mt][2][1]+bb[5],
                                 acc[mt][3][0]+bb[6], acc[mt][3][1]+bb[7]);
        float4 r1a = make_float4(acc[mt][0][2]+bb[0], acc[mt][0][3]+bb[1],
                                 acc[mt][1][2]+bb[2], acc[mt][1][3]+bb[3]);
        float4 r1b = make_float4(acc[mt][2][2]+bb[4], acc[mt][2][3]+bb[5],
                                 acc[mt][3][2]+bb[6], acc[mt][3][3]+bb[7]);
        *reinterpret_cast<float4*>(ob)              = r0a;
        *reinterpret_cast<float4*>(ob + 4)          = r0b;
        *reinterpret_cast<float4*>(ob + 8 * Pn)     = r1a;
        *reinterpret_cast<float4*>(ob + 8 * Pn + 4) = r1b;
    }
}

extern "C" void kernel_launch(void* const* d_in, const int* in_sizes, int n_in,
                              void* d_out, int out_size) {
    (void)in_sizes; (void)n_in; (void)out_size;
    const float* x      = (const float*)d_in[0];
    const float* conv_w = (const float*)d_in[1];
    const float* conv_b = (const float*)d_in[2];
    const float* lin_w  = (const float*)d_in[3];
    const float* lin_b  = (const float*)d_in[4];
    float* out = (float*)d_out;

    pack_w_kernel<<<2, 256>>>(lin_w);

    cudaFuncSetAttribute(encoder_kernel,
                         cudaFuncAttributeMaxDynamicSharedMemorySize, SMEM_TOTAL);
    dim3 grid((unsigned)(Sn / S_TILE), Bn);
    encoder_kernel<<<grid, THREADS, SMEM_TOTAL>>>(x, conv_w, conv_b, lin_b, out);
}